// round 1
// baseline (speedup 1.0000x reference)
#include <cuda_runtime.h>
#include <math.h>

// Shapes: B=256, hn=12, N1=12, dim=inner=1024
// BH = 3072, M = BH*12 = 36864, K = N = 1024 for every big GEMM.
#define MROWS   36864
#define BHCOUNT 3072
#define DIM     1024
#define SLAB    37748736ULL   // MROWS * DIM

// 8 slabs of (36864 x 1024) floats = ~1.21 GB scratch.
// 0: emb_r (-> normed_r -> attn_out_r)   1: emb_t (-> normed_t -> attn_out_t)
// 2: ln_r (-> q_r)                        3: ln_t (-> q_t)
// 4: v_r                                  5: v_t
// 6: k_r                                  7: k_t
__device__ float g_buf[8 * 37748736ULL];
__device__ float g_stats[48];   // [0:12) sum_r, [12:24) sq_r, [24:36) sum_t, [36:48) sq_t
__device__ float g_coef[48];    // [0:12) A_r,  [12:24) B_r,  [24:36) A_t,  [36:48) B_t

// ---------------------------------------------------------------------------
// zero the BN stats accumulators (must run at the start of every launch so
// graph replays are deterministic)
// ---------------------------------------------------------------------------
__global__ void zero_stats_kernel() {
    if (threadIdx.x < 48) g_stats[threadIdx.x] = 0.0f;
}

// ---------------------------------------------------------------------------
// SGEMM: C[M,1024] = A[M,1024] @ W[1024,1024]^T + bias
// W is row-major (out, in) so C[m][n] = sum_k A[m][k] * W[n][k].
// 128x128 block tile, K-tile 8, 256 threads, 8x8 per thread.
// ---------------------------------------------------------------------------
__global__ __launch_bounds__(256) void sgemm_bias_kernel(
    const float* __restrict__ A, const float* __restrict__ W,
    const float* __restrict__ bias, float* __restrict__ C)
{
    __shared__ float As[8][128];
    __shared__ float Bs[8][128];
    const int K = 1024;
    const int tid = threadIdx.x;
    const int tx = tid & 15;
    const int ty = tid >> 4;
    const int bm = blockIdx.y;
    const int bn = blockIdx.x;

    const float* Ab = A + (size_t)bm * 128 * K;
    const float* Wb = W + (size_t)bn * 128 * K;

    const int lrow = tid >> 1;         // 0..127
    const int lcol = (tid & 1) * 4;    // 0 or 4

    float acc[8][8];
#pragma unroll
    for (int i = 0; i < 8; i++)
#pragma unroll
        for (int j = 0; j < 8; j++) acc[i][j] = 0.0f;

    for (int k0 = 0; k0 < K; k0 += 8) {
        float4 av = *(const float4*)(Ab + (size_t)lrow * K + k0 + lcol);
        float4 bv = *(const float4*)(Wb + (size_t)lrow * K + k0 + lcol);
        As[lcol + 0][lrow] = av.x; As[lcol + 1][lrow] = av.y;
        As[lcol + 2][lrow] = av.z; As[lcol + 3][lrow] = av.w;
        Bs[lcol + 0][lrow] = bv.x; Bs[lcol + 1][lrow] = bv.y;
        Bs[lcol + 2][lrow] = bv.z; Bs[lcol + 3][lrow] = bv.w;
        __syncthreads();
#pragma unroll
        for (int kk = 0; kk < 8; kk++) {
            float a[8], b[8];
            *(float4*)&a[0] = *(const float4*)&As[kk][ty * 8];
            *(float4*)&a[4] = *(const float4*)&As[kk][ty * 8 + 4];
            *(float4*)&b[0] = *(const float4*)&Bs[kk][tx * 8];
            *(float4*)&b[4] = *(const float4*)&Bs[kk][tx * 8 + 4];
#pragma unroll
            for (int i = 0; i < 8; i++)
#pragma unroll
                for (int j = 0; j < 8; j++) acc[i][j] += a[i] * b[j];
        }
        __syncthreads();
    }

    const int col0 = bn * 128 + tx * 8;
    float4 bia0 = *(const float4*)(bias + col0);
    float4 bia1 = *(const float4*)(bias + col0 + 4);
#pragma unroll
    for (int i = 0; i < 8; i++) {
        size_t row = (size_t)bm * 128 + ty * 8 + i;
        float4 o0 = make_float4(acc[i][0] + bia0.x, acc[i][1] + bia0.y,
                                acc[i][2] + bia0.z, acc[i][3] + bia0.w);
        float4 o1 = make_float4(acc[i][4] + bia1.x, acc[i][5] + bia1.y,
                                acc[i][6] + bia1.z, acc[i][7] + bia1.w);
        *(float4*)(C + row * K + col0)     = o0;
        *(float4*)(C + row * K + col0 + 4) = o1;
    }
}

// ---------------------------------------------------------------------------
// BN statistics: per-channel (row % 12) sum and sum-of-squares.
// One block per 12 consecutive rows (so block-local row r has channel r).
// ---------------------------------------------------------------------------
__global__ void bn_stats_kernel(const float* __restrict__ x,
                                float* __restrict__ sum_out,  // 12 floats
                                float* __restrict__ sq_out)   // 12 floats
{
    const int row0 = blockIdx.x * 12;
    const int tid = threadIdx.x;       // 256 threads
    const int lane = tid & 31;
    const int wrp = tid >> 5;
    __shared__ float ss[8], sq[8];

    for (int r = 0; r < 12; r++) {
        const float4* p = (const float4*)(x + (size_t)(row0 + r) * DIM);
        float s = 0.0f, q = 0.0f;
        // 256 float4s per row, one per thread
        float4 v = p[tid];
        s = v.x + v.y + v.z + v.w;
        q = v.x * v.x + v.y * v.y + v.z * v.z + v.w * v.w;
#pragma unroll
        for (int o = 16; o; o >>= 1) {
            s += __shfl_xor_sync(0xffffffffu, s, o);
            q += __shfl_xor_sync(0xffffffffu, q, o);
        }
        if (lane == 0) { ss[wrp] = s; sq[wrp] = q; }
        __syncthreads();
        if (tid == 0) {
            float S = 0.0f, Q = 0.0f;
#pragma unroll
            for (int i = 0; i < 8; i++) { S += ss[i]; Q += sq[i]; }
            atomicAdd(&sum_out[r], S);
            atomicAdd(&sq_out[r], Q);
        }
        __syncthreads();
    }
}

// ---------------------------------------------------------------------------
// BN finalize: mean/var -> per-channel affine coefficients (both streams)
// ---------------------------------------------------------------------------
__global__ void bn_finalize_kernel(const float* __restrict__ bn_w,
                                   const float* __restrict__ bn_b)
{
    int c = threadIdx.x;
    if (c >= 12) return;
    const float inv_cnt = 1.0f / 3145728.0f;   // BH * 1024 elements per channel
    // rgb
    {
        float mean = g_stats[c] * inv_cnt;
        float var  = g_stats[12 + c] * inv_cnt - mean * mean;
        float inv  = rsqrtf(var + 1e-5f);
        float A    = bn_w[c] * inv;
        g_coef[c]      = A;
        g_coef[12 + c] = bn_b[c] - mean * A;
    }
    // tir
    {
        float mean = g_stats[24 + c] * inv_cnt;
        float var  = g_stats[36 + c] * inv_cnt - mean * mean;
        float inv  = rsqrtf(var + 1e-5f);
        float A    = bn_w[c] * inv;
        g_coef[24 + c] = A;
        g_coef[36 + c] = bn_b[c] - mean * A;
    }
}

// ---------------------------------------------------------------------------
// BN apply (+ positional embedding), in place.
// pos_emb layout: (1, B, N1, 1024); row = bh*12 + n1, bh = b*12 + h.
// coef_off: 0 for rgb, 24 for tir.
// ---------------------------------------------------------------------------
__global__ void bn_apply_kernel(float* __restrict__ x,
                                const float* __restrict__ pos,
                                int coef_off)
{
    size_t i4 = (size_t)blockIdx.x * 256 + threadIdx.x;  // float4 index
    size_t row = i4 >> 8;                                // /256 float4s per row
    int d4 = (int)(i4 & 255);
    int c = (int)(row % 12);
    size_t b = row / 144;                                // row / (hn*N1)
    float A  = g_coef[coef_off + c];
    float Bc = g_coef[coef_off + 12 + c];
    const float4 p = *(const float4*)(pos + ((b * 12 + c) * (size_t)DIM + d4 * 4));
    float4 v = *(float4*)(x + i4 * 4);
    v.x = v.x * A + Bc + p.x;
    v.y = v.y * A + Bc + p.y;
    v.z = v.z * A + Bc + p.z;
    v.w = v.w * A + Bc + p.w;
    *(float4*)(x + i4 * 4) = v;
}

// ---------------------------------------------------------------------------
// LayerNorm over last dim (1024), one block per row.
// ---------------------------------------------------------------------------
__global__ void ln_kernel(const float* __restrict__ src, float* __restrict__ dst,
                          const float* __restrict__ w, const float* __restrict__ b)
{
    const int row = blockIdx.x;
    const int tid = threadIdx.x;      // 256 threads, one float4 each
    const int lane = tid & 31;
    const int wrp = tid >> 5;
    __shared__ float ss[8], sq[8], mv[2];

    float4 v = ((const float4*)(src + (size_t)row * DIM))[tid];
    float s = v.x + v.y + v.z + v.w;
    float q = v.x * v.x + v.y * v.y + v.z * v.z + v.w * v.w;
#pragma unroll
    for (int o = 16; o; o >>= 1) {
        s += __shfl_xor_sync(0xffffffffu, s, o);
        q += __shfl_xor_sync(0xffffffffu, q, o);
    }
    if (lane == 0) { ss[wrp] = s; sq[wrp] = q; }
    __syncthreads();
    if (tid == 0) {
        float S = 0.0f, Q = 0.0f;
#pragma unroll
        for (int i = 0; i < 8; i++) { S += ss[i]; Q += sq[i]; }
        float mean = S * (1.0f / 1024.0f);
        float var  = Q * (1.0f / 1024.0f) - mean * mean;
        mv[0] = mean;
        mv[1] = rsqrtf(var + 1e-5f);
    }
    __syncthreads();
    float mean = mv[0], inv = mv[1];
    float4 wv = ((const float4*)w)[tid];
    float4 bv = ((const float4*)b)[tid];
    float4 o;
    o.x = (v.x - mean) * inv * wv.x + bv.x;
    o.y = (v.y - mean) * inv * wv.y + bv.y;
    o.z = (v.z - mean) * inv * wv.z + bv.z;
    o.w = (v.w - mean) * inv * wv.w + bv.w;
    ((float4*)(dst + (size_t)row * DIM))[tid] = o;
}

// ---------------------------------------------------------------------------
// Fused per-(bh, stream) attention: logits (12x24) -> softmax -> attn @ V.
// grid = (3072, 2): y==0 rgb, y==1 tir. 256 threads.
// ---------------------------------------------------------------------------
__global__ void attn_kernel(const float* __restrict__ q_r, const float* __restrict__ q_t,
                            const float* __restrict__ k_r, const float* __restrict__ k_t,
                            const float* __restrict__ v_r, const float* __restrict__ v_t,
                            float* __restrict__ ao_r, float* __restrict__ ao_t)
{
    const int bh = blockIdx.x;
    const bool tir = (blockIdx.y != 0);
    const size_t base = (size_t)bh * 12 * DIM;
    const float* Q  = (tir ? q_t : q_r) + base;
    float*       AO = (tir ? ao_t : ao_r) + base;
    const float* Kr = k_r + base;
    const float* Kt = k_t + base;
    const float* Vr = v_r + base;
    const float* Vt = v_t + base;

    __shared__ float att[12][24];
    const int tid = threadIdx.x;
    const int lane = tid & 31;
    const int wrp = tid >> 5;   // 8 warps

    for (int dot = wrp; dot < 288; dot += 8) {
        int n1 = dot / 24;
        int s  = dot % 24;
        const float4* qp = (const float4*)(Q + (size_t)n1 * DIM);
        const float4* kp = (const float4*)((s < 12) ? (Kr + (size_t)s * DIM)
                                                    : (Kt + (size_t)(s - 12) * DIM));
        float acc = 0.0f;
#pragma unroll
        for (int d4 = lane; d4 < 256; d4 += 32) {
            float4 a = qp[d4];
            float4 b = kp[d4];
            acc += a.x * b.x + a.y * b.y + a.z * b.z + a.w * b.w;
        }
#pragma unroll
        for (int o = 16; o; o >>= 1) acc += __shfl_xor_sync(0xffffffffu, acc, o);
        if (lane == 0) att[n1][s] = acc;
    }
    __syncthreads();

    if (tid < 12) {
        const float scale = 0.03125f;   // 1024^-0.5
        float e[24];
        float m = -1e30f;
#pragma unroll
        for (int s = 0; s < 24; s++) {
            float l = att[tid][s] * scale;
            e[s] = l;
            m = fmaxf(m, l);
        }
        float sum = 0.0f;
#pragma unroll
        for (int s = 0; s < 24; s++) { float x = expf(e[s] - m); e[s] = x; sum += x; }
        float inv = 1.0f / sum;
#pragma unroll
        for (int s = 0; s < 24; s++) att[tid][s] = e[s] * inv;
    }
    __syncthreads();

    for (int d = tid; d < DIM; d += 256) {
        float vc[24];
#pragma unroll
        for (int s = 0; s < 12; s++) vc[s]      = Vr[(size_t)s * DIM + d];
#pragma unroll
        for (int s = 0; s < 12; s++) vc[12 + s] = Vt[(size_t)s * DIM + d];
#pragma unroll
        for (int n1 = 0; n1 < 12; n1++) {
            float o = 0.0f;
#pragma unroll
            for (int s = 0; s < 24; s++) o += att[n1][s] * vc[s];
            AO[(size_t)n1 * DIM + d] = o;
        }
    }
}

// ---------------------------------------------------------------------------
// launch
// ---------------------------------------------------------------------------
extern "C" void kernel_launch(void* const* d_in, const int* in_sizes, int n_in,
                              void* d_out, int out_size)
{
    const float* attn_rgb = (const float*)d_in[0];
    const float* attn_tir = (const float*)d_in[1];
    const float* pos_emb  = (const float*)d_in[2];
    const float* embed_w  = (const float*)d_in[3];
    const float* embed_b  = (const float*)d_in[4];
    const float* bn_w     = (const float*)d_in[5];
    const float* bn_b     = (const float*)d_in[6];
    const float* ln_w     = (const float*)d_in[7];
    const float* ln_b     = (const float*)d_in[8];
    const float* v_w      = (const float*)d_in[9];
    const float* v_b      = (const float*)d_in[10];
    const float* q_w      = (const float*)d_in[11];
    const float* q_b      = (const float*)d_in[12];
    const float* k_w      = (const float*)d_in[13];
    const float* k_b      = (const float*)d_in[14];
    const float* out_w    = (const float*)d_in[15];
    const float* out_b    = (const float*)d_in[16];
    float* out = (float*)d_out;

    float* buf = nullptr;
    cudaGetSymbolAddress((void**)&buf, g_buf);
    float* stats = nullptr;
    cudaGetSymbolAddress((void**)&stats, g_stats);

    float* emb_r = buf + 0 * SLAB;   // later reused as attention output (rgb)
    float* emb_t = buf + 1 * SLAB;   // later reused as attention output (tir)
    float* ln_r  = buf + 2 * SLAB;   // later reused as q_r
    float* ln_t  = buf + 3 * SLAB;   // later reused as q_t
    float* vb_r  = buf + 4 * SLAB;
    float* vb_t  = buf + 5 * SLAB;
    float* kb_r  = buf + 6 * SLAB;
    float* kb_t  = buf + 7 * SLAB;

    const dim3 gemm_grid(8, 288);    // N-tiles x M-tiles (M = 36864)

    zero_stats_kernel<<<1, 64>>>();

    // embed GEMMs
    sgemm_bias_kernel<<<gemm_grid, 256>>>(attn_rgb, embed_w, embed_b, emb_r);
    sgemm_bias_kernel<<<gemm_grid, 256>>>(attn_tir, embed_w, embed_b, emb_t);

    // BN stats + finalize + apply (with pos add), in place
    bn_stats_kernel<<<BHCOUNT, 256>>>(emb_r, stats + 0,  stats + 12);
    bn_stats_kernel<<<BHCOUNT, 256>>>(emb_t, stats + 24, stats + 36);
    bn_finalize_kernel<<<1, 32>>>(bn_w, bn_b);
    bn_apply_kernel<<<36864, 256>>>(emb_r, pos_emb, 0);
    bn_apply_kernel<<<36864, 256>>>(emb_t, pos_emb, 24);

    // LayerNorm of raw inputs -> value GEMMs
    ln_kernel<<<MROWS, 256>>>(attn_rgb, ln_r, ln_w, ln_b);
    ln_kernel<<<MROWS, 256>>>(attn_tir, ln_t, ln_w, ln_b);
    sgemm_bias_kernel<<<gemm_grid, 256>>>(ln_r, v_w, v_b, vb_r);
    sgemm_bias_kernel<<<gemm_grid, 256>>>(ln_t, v_w, v_b, vb_t);

    // Q GEMMs (overwrite ln buffers) and K GEMMs
    sgemm_bias_kernel<<<gemm_grid, 256>>>(emb_r, q_w, q_b, ln_r);
    sgemm_bias_kernel<<<gemm_grid, 256>>>(emb_t, q_w, q_b, ln_t);
    sgemm_bias_kernel<<<gemm_grid, 256>>>(emb_r, k_w, k_b, kb_r);
    sgemm_bias_kernel<<<gemm_grid, 256>>>(emb_t, k_w, k_b, kb_t);

    // fused softmax attention; writes attention output into emb buffers
    attn_kernel<<<dim3(BHCOUNT, 2), 256>>>(ln_r, ln_t, kb_r, kb_t, vb_r, vb_t,
                                           emb_r, emb_t);

    // output projection straight into d_out (rgb first, then tir)
    sgemm_bias_kernel<<<gemm_grid, 256>>>(emb_r, out_w, out_b, out);
    sgemm_bias_kernel<<<gemm_grid, 256>>>(emb_t, out_w, out_b, out + SLAB);
}

// round 4
// speedup vs baseline: 1.8893x; 1.8893x over previous
#include <cuda_runtime.h>
#include <cuda_bf16.h>
#include <math.h>
#include <stdint.h>

// Shapes: B=256, hn=12, N1=12, dim=inner=1024
#define MROWS   36864
#define BHCOUNT 3072
#define DIM     1024
#define SLAB    37748736ULL          // MROWS * DIM
#define KS      2048                 // split row length (hi|lo)

// fp32 slabs: 0 emb_r, 1 emb_t, 2 q_r, 3 q_t, 4 k_r, 5 k_t, 6 v_r, 7 v_t
__device__ float g_f32[8 * SLAB];
// bf16 split slabs (each SLAB*2 elems): 0 in_r, 1 in_t, 2 norm_r, 3 norm_t,
// 4 ln_r, 5 ln_t, 6 ao_r, 7 ao_t
__device__ __nv_bfloat16 g_split[8ULL * SLAB * 2];
// weight splits: 0 embed, 1 v, 2 q, 3 k, 4 out  (each [1024][2048])
__device__ __nv_bfloat16 g_wsplit[5ULL * 1024 * 2048];
__device__ float g_stats[48];
__device__ float g_coef[48];

// ---------------------------------------------------------------------------
__global__ void zero_stats_kernel() {
    if (threadIdx.x < 48) g_stats[threadIdx.x] = 0.0f;
}

// ---------------------------------------------------------------------------
// helpers
// ---------------------------------------------------------------------------
__device__ __forceinline__ uint32_t swz128(uint32_t o) { return o ^ ((o >> 3) & 0x70); }

__device__ __forceinline__ void cp_async16(uint32_t saddr, const void* gaddr) {
    asm volatile("cp.async.cg.shared.global [%0], [%1], 16;\n" :: "r"(saddr), "l"(gaddr));
}
__device__ __forceinline__ void cp_commit() { asm volatile("cp.async.commit_group;\n"); }

__device__ __forceinline__ void ldsm4(uint32_t& r0, uint32_t& r1, uint32_t& r2,
                                      uint32_t& r3, uint32_t addr) {
    asm volatile("ldmatrix.sync.aligned.m8n8.x4.shared.b16 {%0,%1,%2,%3}, [%4];\n"
                 : "=r"(r0), "=r"(r1), "=r"(r2), "=r"(r3) : "r"(addr));
}

__device__ __forceinline__ void mma16816(float* d, const uint32_t* a, const uint32_t* b) {
    asm volatile(
        "mma.sync.aligned.m16n8k16.row.col.f32.bf16.bf16.f32 "
        "{%0,%1,%2,%3},{%4,%5,%6,%7},{%8,%9},{%0,%1,%2,%3};\n"
        : "+f"(d[0]), "+f"(d[1]), "+f"(d[2]), "+f"(d[3])
        : "r"(a[0]), "r"(a[1]), "r"(a[2]), "r"(a[3]), "r"(b[0]), "r"(b[1]));
}

__device__ __forceinline__ void split1(float v, __nv_bfloat16& h, __nv_bfloat16& l) {
    h = __float2bfloat16(v);
    l = __float2bfloat16(v - __bfloat162float(h));
}

// ---------------------------------------------------------------------------
// split a [rows][1024] fp32 matrix into [rows][2048] bf16 (hi | lo)
// grid = rows, block = 256 (one float4 per thread)
// ---------------------------------------------------------------------------
__global__ void split_rows_kernel(const float* __restrict__ in,
                                  __nv_bfloat16* __restrict__ out)
{
    size_t row = blockIdx.x;
    int t = threadIdx.x;
    float4 v = ((const float4*)(in + row * DIM))[t];
    __nv_bfloat16 h[4], l[4];
    split1(v.x, h[0], l[0]); split1(v.y, h[1], l[1]);
    split1(v.z, h[2], l[2]); split1(v.w, h[3], l[3]);
    *(uint2*)(out + row * KS + t * 4)        = *(uint2*)h;
    *(uint2*)(out + row * KS + 1024 + t * 4) = *(uint2*)l;
}

// ---------------------------------------------------------------------------
// split-GEMM: C[M,1024] = A32 @ W32^T + bias, done as three bf16 products
//   A buffer [M][2048] = (A_hi | A_lo), W buffer [1024][2048] = (W_hi | W_lo)
//   segments: (hi,hi), (hi,lo), (lo,hi)
// block tile 128x128, k-tile 64, 256 threads (8 warps, warp tile 32x64)
// ---------------------------------------------------------------------------
#define STAGE_BYTES 32768
#define NKT 48

__global__ __launch_bounds__(256, 2) void hgemm3_kernel(
    const __nv_bfloat16* __restrict__ A, const __nv_bfloat16* __restrict__ W,
    const float* __restrict__ bias, float* __restrict__ C)
{
    extern __shared__ char smem[];
    uint32_t sbase;
    asm("{ .reg .u64 t; cvta.to.shared.u64 t, %1; cvt.u32.u64 %0, t; }"
        : "=r"(sbase) : "l"(smem));

    const int tid = threadIdx.x, lane = tid & 31, warp = tid >> 5;
    const int bm = blockIdx.y, bn = blockIdx.x;
    const int m_off = (warp >> 1) * 32, n_off = (warp & 1) * 64;

    // load mapping: thread handles chunks (tid + 256*j): row = r0+32j, chunk ch
    const int r0 = tid >> 3;       // 0..31
    const int ch = tid & 7;        // 16B chunk within 128B row

    float acc[2][8][4];
#pragma unroll
    for (int i = 0; i < 2; i++)
#pragma unroll
        for (int j = 0; j < 8; j++)
#pragma unroll
            for (int r = 0; r < 4; r++) acc[i][j][r] = 0.0f;

    auto load_stage = [&](int stage, int kt) {
        int seg = kt >> 4, kk = kt & 15;
        int ka = ((seg == 2) ? 1024 : 0) + kk * 64;
        int kb = ((seg == 1) ? 1024 : 0) + kk * 64;
        const __nv_bfloat16* Ag = A + (size_t)(bm * 128 + r0) * KS + ka + ch * 8;
        const __nv_bfloat16* Wg = W + (size_t)(bn * 128 + r0) * KS + kb + ch * 8;
        uint32_t sa = sbase + stage * STAGE_BYTES;
        uint32_t sb = sa + 16384;
#pragma unroll
        for (int j = 0; j < 4; j++) {
            uint32_t so = swz128((uint32_t)(r0 + 32 * j) * 128 + ch * 16);
            cp_async16(sa + so, Ag + (size_t)(32 * j) * KS);
            cp_async16(sb + so, Wg + (size_t)(32 * j) * KS);
        }
        cp_commit();
    };

    load_stage(0, 0);

    for (int kt = 0; kt < NKT; kt++) {
        if (kt + 1 < NKT) load_stage((kt + 1) & 1, kt + 1);
        if (kt + 1 < NKT) asm volatile("cp.async.wait_group 1;\n");
        else              asm volatile("cp.async.wait_group 0;\n");
        __syncthreads();

        uint32_t sa = sbase + (kt & 1) * STAGE_BYTES;
        uint32_t sb = sa + 16384;
#pragma unroll
        for (int kk16 = 0; kk16 < 4; kk16++) {
            uint32_t afr[2][4], bfr[8][2];
#pragma unroll
            for (int i = 0; i < 2; i++) {
                int row = m_off + i * 16 + (lane & 15);
                uint32_t addr = sa + swz128((uint32_t)row * 128 + kk16 * 32 + ((lane >> 4) << 4));
                ldsm4(afr[i][0], afr[i][1], afr[i][2], afr[i][3], addr);
            }
#pragma unroll
            for (int jj = 0; jj < 4; jj++) {
                int row = n_off + jj * 16 + (lane & 7) + ((lane >> 4) << 3);
                uint32_t addr = sb + swz128((uint32_t)row * 128 + kk16 * 32 + (((lane >> 3) & 1) << 4));
                ldsm4(bfr[2 * jj][0], bfr[2 * jj][1], bfr[2 * jj + 1][0], bfr[2 * jj + 1][1], addr);
            }
#pragma unroll
            for (int i = 0; i < 2; i++)
#pragma unroll
                for (int j = 0; j < 8; j++) mma16816(acc[i][j], afr[i], bfr[j]);
        }
        __syncthreads();
    }

    // epilogue
    const int gr = lane >> 2, gc = (lane & 3) * 2;
#pragma unroll
    for (int i = 0; i < 2; i++) {
        size_t rowg = (size_t)(bm * 128 + m_off + i * 16 + gr);
#pragma unroll
        for (int j = 0; j < 8; j++) {
            int col = bn * 128 + n_off + j * 8 + gc;
            float b0 = __ldg(bias + col), b1 = __ldg(bias + col + 1);
            float2 o0 = make_float2(acc[i][j][0] + b0, acc[i][j][1] + b1);
            float2 o1 = make_float2(acc[i][j][2] + b0, acc[i][j][3] + b1);
            *(float2*)(C + rowg * DIM + col)       = o0;
            *(float2*)(C + (rowg + 8) * DIM + col) = o1;
        }
    }
}

// ---------------------------------------------------------------------------
// BN statistics: per-channel (row % 12) sum and sum-of-squares
// ---------------------------------------------------------------------------
__global__ void bn_stats_kernel(const float* __restrict__ x,
                                float* __restrict__ sum_out, float* __restrict__ sq_out)
{
    const int row0 = blockIdx.x * 12;
    const int tid = threadIdx.x, lane = tid & 31, wrp = tid >> 5;
    __shared__ float ss[8], sq[8];
    for (int r = 0; r < 12; r++) {
        const float4* p = (const float4*)(x + (size_t)(row0 + r) * DIM);
        float4 v = p[tid];
        float s = v.x + v.y + v.z + v.w;
        float q = v.x * v.x + v.y * v.y + v.z * v.z + v.w * v.w;
#pragma unroll
        for (int o = 16; o; o >>= 1) {
            s += __shfl_xor_sync(0xffffffffu, s, o);
            q += __shfl_xor_sync(0xffffffffu, q, o);
        }
        if (lane == 0) { ss[wrp] = s; sq[wrp] = q; }
        __syncthreads();
        if (tid == 0) {
            float S = 0.0f, Q = 0.0f;
#pragma unroll
            for (int i = 0; i < 8; i++) { S += ss[i]; Q += sq[i]; }
            atomicAdd(&sum_out[r], S);
            atomicAdd(&sq_out[r], Q);
        }
        __syncthreads();
    }
}

__global__ void bn_finalize_kernel(const float* __restrict__ bn_w,
                                   const float* __restrict__ bn_b)
{
    int c = threadIdx.x;
    if (c >= 12) return;
    const float inv_cnt = 1.0f / 3145728.0f;
    {
        float mean = g_stats[c] * inv_cnt;
        float var  = g_stats[12 + c] * inv_cnt - mean * mean;
        float A = bn_w[c] * rsqrtf(var + 1e-5f);
        g_coef[c] = A;  g_coef[12 + c] = bn_b[c] - mean * A;
    }
    {
        float mean = g_stats[24 + c] * inv_cnt;
        float var  = g_stats[36 + c] * inv_cnt - mean * mean;
        float A = bn_w[c] * rsqrtf(var + 1e-5f);
        g_coef[24 + c] = A;  g_coef[36 + c] = bn_b[c] - mean * A;
    }
}

// ---------------------------------------------------------------------------
// BN apply + pos add, write split bf16 [row][2048]. grid = MROWS, block 256.
// ---------------------------------------------------------------------------
__global__ void bn_apply_split_kernel(const float* __restrict__ x,
                                      const float* __restrict__ pos,
                                      __nv_bfloat16* __restrict__ out, int coef_off)
{
    size_t row = blockIdx.x;
    int t = threadIdx.x;
    int c = (int)(row % 12);
    size_t b = row / 144;
    float A  = g_coef[coef_off + c];
    float Bc = g_coef[coef_off + 12 + c];
    float4 v = ((const float4*)(x + row * DIM))[t];
    float4 p = ((const float4*)(pos + (b * 12 + (size_t)c) * DIM))[t];
    float y0 = v.x * A + Bc + p.x, y1 = v.y * A + Bc + p.y;
    float y2 = v.z * A + Bc + p.z, y3 = v.w * A + Bc + p.w;
    __nv_bfloat16 h[4], l[4];
    split1(y0, h[0], l[0]); split1(y1, h[1], l[1]);
    split1(y2, h[2], l[2]); split1(y3, h[3], l[3]);
    *(uint2*)(out + row * KS + t * 4)        = *(uint2*)h;
    *(uint2*)(out + row * KS + 1024 + t * 4) = *(uint2*)l;
}

// ---------------------------------------------------------------------------
// LayerNorm -> split bf16 output. grid = MROWS, block 256.
// ---------------------------------------------------------------------------
__global__ void ln_split_kernel(const float* __restrict__ src,
                                __nv_bfloat16* __restrict__ dst,
                                const float* __restrict__ w, const float* __restrict__ b)
{
    const size_t row = blockIdx.x;
    const int tid = threadIdx.x, lane = tid & 31, wrp = tid >> 5;
    __shared__ float ss[8], sq[8], mv[2];
    float4 v = ((const float4*)(src + row * DIM))[tid];
    float s = v.x + v.y + v.z + v.w;
    float q = v.x * v.x + v.y * v.y + v.z * v.z + v.w * v.w;
#pragma unroll
    for (int o = 16; o; o >>= 1) {
        s += __shfl_xor_sync(0xffffffffu, s, o);
        q += __shfl_xor_sync(0xffffffffu, q, o);
    }
    if (lane == 0) { ss[wrp] = s; sq[wrp] = q; }
    __syncthreads();
    if (tid == 0) {
        float S = 0.0f, Q = 0.0f;
#pragma unroll
        for (int i = 0; i < 8; i++) { S += ss[i]; Q += sq[i]; }
        float mean = S * (1.0f / 1024.0f);
        float var  = Q * (1.0f / 1024.0f) - mean * mean;
        mv[0] = mean;  mv[1] = rsqrtf(var + 1e-5f);
    }
    __syncthreads();
    float mean = mv[0], inv = mv[1];
    float4 wv = ((const float4*)w)[tid];
    float4 bv = ((const float4*)b)[tid];
    float y0 = (v.x - mean) * inv * wv.x + bv.x;
    float y1 = (v.y - mean) * inv * wv.y + bv.y;
    float y2 = (v.z - mean) * inv * wv.z + bv.z;
    float y3 = (v.w - mean) * inv * wv.w + bv.w;
    __nv_bfloat16 h[4], l[4];
    split1(y0, h[0], l[0]); split1(y1, h[1], l[1]);
    split1(y2, h[2], l[2]); split1(y3, h[3], l[3]);
    *(uint2*)(dst + row * KS + tid * 4)        = *(uint2*)h;
    *(uint2*)(dst + row * KS + 1024 + tid * 4) = *(uint2*)l;
}

// ---------------------------------------------------------------------------
// fused attention: logits(12x24) -> softmax -> attn @ V; output split bf16
// ---------------------------------------------------------------------------
__global__ void attn_kernel(const float* __restrict__ q_r, const float* __restrict__ q_t,
                            const float* __restrict__ k_r, const float* __restrict__ k_t,
                            const float* __restrict__ v_r, const float* __restrict__ v_t,
                            __nv_bfloat16* __restrict__ ao_r, __nv_bfloat16* __restrict__ ao_t)
{
    const int bh = blockIdx.x;
    const bool tir = (blockIdx.y != 0);
    const size_t base = (size_t)bh * 12 * DIM;
    const float* Q = (tir ? q_t : q_r) + base;
    __nv_bfloat16* AO = (tir ? ao_t : ao_r) + (size_t)bh * 12 * KS;
    const float* Kr = k_r + base;
    const float* Kt = k_t + base;
    const float* Vr = v_r + base;
    const float* Vt = v_t + base;

    __shared__ float att[12][24];
    const int tid = threadIdx.x, lane = tid & 31, wrp = tid >> 5;

    for (int dot = wrp; dot < 288; dot += 8) {
        int n1 = dot / 24, s = dot % 24;
        const float4* qp = (const float4*)(Q + (size_t)n1 * DIM);
        const float4* kp = (const float4*)((s < 12) ? (Kr + (size_t)s * DIM)
                                                    : (Kt + (size_t)(s - 12) * DIM));
        float acc = 0.0f;
        for (int d4 = lane; d4 < 256; d4 += 32) {
            float4 a = qp[d4]; float4 bb = kp[d4];
            acc += a.x * bb.x + a.y * bb.y + a.z * bb.z + a.w * bb.w;
        }
#pragma unroll
        for (int o = 16; o; o >>= 1) acc += __shfl_xor_sync(0xffffffffu, acc, o);
        if (lane == 0) att[n1][s] = acc;
    }
    __syncthreads();

    if (tid < 12) {
        const float scale = 0.03125f;
        float e[24], m = -1e30f;
#pragma unroll
        for (int s = 0; s < 24; s++) { float l = att[tid][s] * scale; e[s] = l; m = fmaxf(m, l); }
        float sum = 0.0f;
#pragma unroll
        for (int s = 0; s < 24; s++) { float x = expf(e[s] - m); e[s] = x; sum += x; }
        float inv = 1.0f / sum;
#pragma unroll
        for (int s = 0; s < 24; s++) att[tid][s] = e[s] * inv;
    }
    __syncthreads();

    for (int d = tid; d < DIM; d += 256) {
        float vc[24];
#pragma unroll
        for (int s = 0; s < 12; s++) vc[s]      = Vr[(size_t)s * DIM + d];
#pragma unroll
        for (int s = 0; s < 12; s++) vc[12 + s] = Vt[(size_t)s * DIM + d];
#pragma unroll
        for (int n1 = 0; n1 < 12; n1++) {
            float o = 0.0f;
#pragma unroll
            for (int s = 0; s < 24; s++) o += att[n1][s] * vc[s];
            __nv_bfloat16 h, l;
            split1(o, h, l);
            AO[(size_t)n1 * KS + d]        = h;
            AO[(size_t)n1 * KS + 1024 + d] = l;
        }
    }
}

// ---------------------------------------------------------------------------
extern "C" void kernel_launch(void* const* d_in, const int* in_sizes, int n_in,
                              void* d_out, int out_size)
{
    const float* attn_rgb = (const float*)d_in[0];
    const float* attn_tir = (const float*)d_in[1];
    const float* pos_emb  = (const float*)d_in[2];
    const float* embed_w  = (const float*)d_in[3];
    const float* embed_b  = (const float*)d_in[4];
    const float* bn_w     = (const float*)d_in[5];
    const float* bn_b     = (const float*)d_in[6];
    const float* ln_w     = (const float*)d_in[7];
    const float* ln_b     = (const float*)d_in[8];
    const float* v_w      = (const float*)d_in[9];
    const float* v_b      = (const float*)d_in[10];
    const float* q_w      = (const float*)d_in[11];
    const float* q_b      = (const float*)d_in[12];
    const float* k_w      = (const float*)d_in[13];
    const float* k_b      = (const float*)d_in[14];
    const float* out_w    = (const float*)d_in[15];
    const float* out_b    = (const float*)d_in[16];
    float* out = (float*)d_out;

    float* f32 = nullptr;          cudaGetSymbolAddress((void**)&f32, g_f32);
    __nv_bfloat16* sp = nullptr;   cudaGetSymbolAddress((void**)&sp, g_split);
    __nv_bfloat16* ws = nullptr;   cudaGetSymbolAddress((void**)&ws, g_wsplit);
    float* stats = nullptr;        cudaGetSymbolAddress((void**)&stats, g_stats);

    float* emb_r = f32 + 0 * SLAB;  float* emb_t = f32 + 1 * SLAB;
    float* q_rf  = f32 + 2 * SLAB;  float* q_tf  = f32 + 3 * SLAB;
    float* k_rf  = f32 + 4 * SLAB;  float* k_tf  = f32 + 5 * SLAB;
    float* v_rf  = f32 + 6 * SLAB;  float* v_tf  = f32 + 7 * SLAB;

    const size_t SS = SLAB * 2;
    __nv_bfloat16* in_r   = sp + 0 * SS;  __nv_bfloat16* in_t   = sp + 1 * SS;
    __nv_bfloat16* norm_r = sp + 2 * SS;  __nv_bfloat16* norm_t = sp + 3 * SS;
    __nv_bfloat16* lns_r  = sp + 4 * SS;  __nv_bfloat16* lns_t  = sp + 5 * SS;
    __nv_bfloat16* ao_r   = sp + 6 * SS;  __nv_bfloat16* ao_t   = sp + 7 * SS;

    const size_t WSS = 1024ULL * 2048;
    __nv_bfloat16* w_embed = ws + 0 * WSS;
    __nv_bfloat16* w_v     = ws + 1 * WSS;
    __nv_bfloat16* w_q     = ws + 2 * WSS;
    __nv_bfloat16* w_k     = ws + 3 * WSS;
    __nv_bfloat16* w_out   = ws + 4 * WSS;

    static bool attr_set = false;
    if (!attr_set) {
        cudaFuncSetAttribute(hgemm3_kernel,
                             cudaFuncAttributeMaxDynamicSharedMemorySize, 2 * STAGE_BYTES);
        attr_set = true;
    }

    const dim3 gemm_grid(8, 288);
    const int GS = 2 * STAGE_BYTES;

    zero_stats_kernel<<<1, 64>>>();

    // splits: weights + raw inputs
    split_rows_kernel<<<1024, 256>>>(embed_w, w_embed);
    split_rows_kernel<<<1024, 256>>>(v_w, w_v);
    split_rows_kernel<<<1024, 256>>>(q_w, w_q);
    split_rows_kernel<<<1024, 256>>>(k_w, w_k);
    split_rows_kernel<<<1024, 256>>>(out_w, w_out);
    split_rows_kernel<<<MROWS, 256>>>(attn_rgb, in_r);
    split_rows_kernel<<<MROWS, 256>>>(attn_tir, in_t);

    // embed GEMMs
    hgemm3_kernel<<<gemm_grid, 256, GS>>>(in_r, w_embed, embed_b, emb_r);
    hgemm3_kernel<<<gemm_grid, 256, GS>>>(in_t, w_embed, embed_b, emb_t);

    // BN stats + apply (+pos), writing split buffers
    bn_stats_kernel<<<BHCOUNT, 256>>>(emb_r, stats + 0,  stats + 12);
    bn_stats_kernel<<<BHCOUNT, 256>>>(emb_t, stats + 24, stats + 36);
    bn_finalize_kernel<<<1, 32>>>(bn_w, bn_b);
    bn_apply_split_kernel<<<MROWS, 256>>>(emb_r, pos_emb, norm_r, 0);
    bn_apply_split_kernel<<<MROWS, 256>>>(emb_t, pos_emb, norm_t, 24);

    // LN -> split, then V GEMMs
    ln_split_kernel<<<MROWS, 256>>>(attn_rgb, lns_r, ln_w, ln_b);
    ln_split_kernel<<<MROWS, 256>>>(attn_tir, lns_t, ln_w, ln_b);
    hgemm3_kernel<<<gemm_grid, 256, GS>>>(lns_r, w_v, v_b, v_rf);
    hgemm3_kernel<<<gemm_grid, 256, GS>>>(lns_t, w_v, v_b, v_tf);

    // Q and K GEMMs from normed buffers
    hgemm3_kernel<<<gemm_grid, 256, GS>>>(norm_r, w_q, q_b, q_rf);
    hgemm3_kernel<<<gemm_grid, 256, GS>>>(norm_t, w_q, q_b, q_tf);
    hgemm3_kernel<<<gemm_grid, 256, GS>>>(norm_r, w_k, k_b, k_rf);
    hgemm3_kernel<<<gemm_grid, 256, GS>>>(norm_t, w_k, k_b, k_tf);

    // fused attention -> split bf16 outputs
    attn_kernel<<<dim3(BHCOUNT, 2), 256>>>(q_rf, q_tf, k_rf, k_tf, v_rf, v_tf,
                                           ao_r, ao_t);

    // output projections straight into d_out
    hgemm3_kernel<<<gemm_grid, 256, GS>>>(ao_r, w_out, out_b, out);
    hgemm3_kernel<<<gemm_grid, 256, GS>>>(ao_t, w_out, out_b, out + SLAB);
}

// round 11
// speedup vs baseline: 3.6822x; 1.9490x over previous
#include <cuda_runtime.h>
#include <cuda_bf16.h>
#include <math.h>
#include <stdint.h>

// Shapes: B=256, hn=12, N1=12, dim=inner=1024
#define MROWS   36864
#define BHCOUNT 3072
#define DIM     1024
#define SLAB    37748736ULL          // MROWS * DIM

// fp32 slabs (all tf32-rounded where they feed a GEMM):
// 0 in_r, 1 in_t, 2 emb_r, 3 emb_t, 4 norm_r, 5 norm_t,
// 6 ln_r (-> ao_r), 7 ln_t (-> ao_t), 8 q_r, 9 q_t, 10 k_r, 11 k_t, 12 v_r, 13 v_t
__device__ float g_f32[14 * SLAB];
__device__ float g_w[5ULL * 1024 * 1024];   // tf32-rounded weights
__device__ float g_stats[48];
__device__ float g_coef[48];

// ---------------------------------------------------------------------------
__global__ void zero_stats_kernel() {
    if (threadIdx.x < 48) g_stats[threadIdx.x] = 0.0f;
}

// ---------------------------------------------------------------------------
// helpers
// ---------------------------------------------------------------------------
__device__ __forceinline__ uint32_t swz128(uint32_t o) { return o ^ ((o >> 3) & 0x70); }

__device__ __forceinline__ void cp_async16(uint32_t saddr, const void* gaddr) {
    asm volatile("cp.async.cg.shared.global [%0], [%1], 16;\n" :: "r"(saddr), "l"(gaddr));
}
__device__ __forceinline__ void cp_commit() { asm volatile("cp.async.commit_group;\n"); }

__device__ __forceinline__ float to_tf32(float x) {
    float r;
    asm("cvt.rna.tf32.f32 %0, %1;" : "=f"(r) : "f"(x));
    return r;
}

__device__ __forceinline__ void ldsm4(uint32_t& r0, uint32_t& r1, uint32_t& r2,
                                      uint32_t& r3, uint32_t addr) {
    asm volatile("ldmatrix.sync.aligned.m8n8.x4.shared.b16 {%0,%1,%2,%3}, [%4];\n"
                 : "=r"(r0), "=r"(r1), "=r"(r2), "=r"(r3) : "r"(addr));
}

__device__ __forceinline__ void mma_tf32(float* d, const uint32_t* a, const uint32_t* b) {
    asm volatile(
        "mma.sync.aligned.m16n8k8.row.col.f32.tf32.tf32.f32 "
        "{%0,%1,%2,%3},{%4,%5,%6,%7},{%8,%9},{%0,%1,%2,%3};\n"
        : "+f"(d[0]), "+f"(d[1]), "+f"(d[2]), "+f"(d[3])
        : "r"(a[0]), "r"(a[1]), "r"(a[2]), "r"(a[3]), "r"(b[0]), "r"(b[1]));
}

__device__ __forceinline__ uint32_t smem_u32(const void* p) {
    uint32_t a;
    asm("{ .reg .u64 t; cvta.to.shared.u64 t, %1; cvt.u32.u64 %0, t; }" : "=r"(a) : "l"(p));
    return a;
}

// ---------------------------------------------------------------------------
// round an fp32 array to tf32 (RN). grid = n/1024, block 256, float4/thread.
// ---------------------------------------------------------------------------
__global__ void cvt_tf32_kernel(const float* __restrict__ in, float* __restrict__ out)
{
    size_t i = ((size_t)blockIdx.x * 256 + threadIdx.x) * 4;
    float4 v = *(const float4*)(in + i);
    v.x = to_tf32(v.x); v.y = to_tf32(v.y);
    v.z = to_tf32(v.z); v.w = to_tf32(v.w);
    *(float4*)(out + i) = v;
}

// ---------------------------------------------------------------------------
// tf32 GEMM: C[M,1024] = A @ W^T + bias (A, W already tf32-rounded fp32).
// Block tile 128x128, k-tile 32 floats (128B rows), 3-stage cp.async.
// 256 threads, 8 warps, warp tile 32x64. mma.m16n8k8.tf32.
// ---------------------------------------------------------------------------
#define TFSTAGE 32768
#define TF_SMEM (3 * TFSTAGE)

__global__ __launch_bounds__(256, 2) void tgemm_kernel(
    const float* __restrict__ A, const float* __restrict__ W,
    const float* __restrict__ bias, float* __restrict__ C)
{
    extern __shared__ char smem[];
    const uint32_t tiles = smem_u32(smem);
    const int tid = threadIdx.x, lane = tid & 31, warp = tid >> 5;
    const int bm = blockIdx.y, bn = blockIdx.x;
    const int m_off = (warp >> 1) * 32, n_off = (warp & 1) * 64;
    const int r0 = tid >> 3;     // 0..31
    const int ch = tid & 7;      // 16B chunk within 128B row

    float acc[2][8][4];
#pragma unroll
    for (int i = 0; i < 2; i++)
#pragma unroll
        for (int j = 0; j < 8; j++)
#pragma unroll
            for (int r = 0; r < 4; r++) acc[i][j][r] = 0.0f;

    auto load_tile = [&](int stage, int kt) {
        const float* Ag = A + (size_t)(bm * 128 + r0) * DIM + kt * 32 + ch * 4;
        const float* Wg = W + (size_t)(bn * 128 + r0) * DIM + kt * 32 + ch * 4;
        uint32_t sa = tiles + stage * TFSTAGE;
        uint32_t sb = sa + 16384;
#pragma unroll
        for (int j = 0; j < 4; j++) {
            uint32_t so = swz128((uint32_t)(r0 + 32 * j) * 128 + ch * 16);
            cp_async16(sa + so, Ag + (size_t)(32 * j) * DIM);
            cp_async16(sb + so, Wg + (size_t)(32 * j) * DIM);
        }
        cp_commit();
    };

    load_tile(0, 0); load_tile(1, 1); load_tile(2, 2);

    for (int kt = 0; kt < 32; kt++) {
        if (kt < 30)       asm volatile("cp.async.wait_group 2;\n" ::: "memory");
        else if (kt == 30) asm volatile("cp.async.wait_group 1;\n" ::: "memory");
        else               asm volatile("cp.async.wait_group 0;\n" ::: "memory");
        __syncthreads();

        uint32_t sa = tiles + (kt % 3) * TFSTAGE;
        uint32_t sb = sa + 16384;
#pragma unroll
        for (int kk = 0; kk < 4; kk++) {           // 4 k8 steps per 32-float tile
            uint32_t afr[2][4], bfr[8][2];
#pragma unroll
            for (int i = 0; i < 2; i++) {
                int row = m_off + i * 16 + (lane & 15);
                uint32_t addr = sa + swz128((uint32_t)row * 128 + (2 * kk + (lane >> 4)) * 16);
                ldsm4(afr[i][0], afr[i][1], afr[i][2], afr[i][3], addr);
            }
#pragma unroll
            for (int jj = 0; jj < 4; jj++) {
                int row = n_off + jj * 16 + (lane & 7) + ((lane >> 4) << 3);
                uint32_t addr = sb + swz128((uint32_t)row * 128 + (2 * kk + ((lane >> 3) & 1)) * 16);
                ldsm4(bfr[2 * jj][0], bfr[2 * jj][1], bfr[2 * jj + 1][0], bfr[2 * jj + 1][1], addr);
            }
#pragma unroll
            for (int i = 0; i < 2; i++)
#pragma unroll
                for (int j = 0; j < 8; j++) mma_tf32(acc[i][j], afr[i], bfr[j]);
        }
        __syncthreads();
        if (kt + 3 < 32) load_tile(kt % 3, kt + 3);
    }

    // epilogue
    const int gr = lane >> 2, gc = (lane & 3) * 2;
#pragma unroll
    for (int i = 0; i < 2; i++) {
        size_t rowg = (size_t)(bm * 128 + m_off + i * 16 + gr);
#pragma unroll
        for (int j = 0; j < 8; j++) {
            int col = bn * 128 + n_off + j * 8 + gc;
            float b0 = __ldg(bias + col), b1 = __ldg(bias + col + 1);
            float2 o0 = make_float2(acc[i][j][0] + b0, acc[i][j][1] + b1);
            float2 o1 = make_float2(acc[i][j][2] + b0, acc[i][j][3] + b1);
            *(float2*)(C + rowg * DIM + col)       = o0;
            *(float2*)(C + (rowg + 8) * DIM + col) = o1;
        }
    }
}

// ---------------------------------------------------------------------------
// BN statistics: per-channel (row % 12) sum and sum-of-squares
// ---------------------------------------------------------------------------
__global__ void bn_stats_kernel(const float* __restrict__ x,
                                float* __restrict__ sum_out, float* __restrict__ sq_out)
{
    const int row0 = blockIdx.x * 12;
    const int tid = threadIdx.x, lane = tid & 31, wrp = tid >> 5;
    __shared__ float ss[8], sq[8];
    for (int r = 0; r < 12; r++) {
        const float4* p = (const float4*)(x + (size_t)(row0 + r) * DIM);
        float4 v = p[tid];
        float s = v.x + v.y + v.z + v.w;
        float q = v.x * v.x + v.y * v.y + v.z * v.z + v.w * v.w;
#pragma unroll
        for (int o = 16; o; o >>= 1) {
            s += __shfl_xor_sync(0xffffffffu, s, o);
            q += __shfl_xor_sync(0xffffffffu, q, o);
        }
        if (lane == 0) { ss[wrp] = s; sq[wrp] = q; }
        __syncthreads();
        if (tid == 0) {
            float S = 0.0f, Q = 0.0f;
#pragma unroll
            for (int i = 0; i < 8; i++) { S += ss[i]; Q += sq[i]; }
            atomicAdd(&sum_out[r], S);
            atomicAdd(&sq_out[r], Q);
        }
        __syncthreads();
    }
}

__global__ void bn_finalize_kernel(const float* __restrict__ bn_w,
                                   const float* __restrict__ bn_b)
{
    int c = threadIdx.x;
    if (c >= 12) return;
    const float inv_cnt = 1.0f / 3145728.0f;
    {
        float mean = g_stats[c] * inv_cnt;
        float var  = g_stats[12 + c] * inv_cnt - mean * mean;
        float A = bn_w[c] * rsqrtf(var + 1e-5f);
        g_coef[c] = A;  g_coef[12 + c] = bn_b[c] - mean * A;
    }
    {
        float mean = g_stats[24 + c] * inv_cnt;
        float var  = g_stats[36 + c] * inv_cnt - mean * mean;
        float A = bn_w[c] * rsqrtf(var + 1e-5f);
        g_coef[24 + c] = A;  g_coef[36 + c] = bn_b[c] - mean * A;
    }
}

// ---------------------------------------------------------------------------
// BN apply + pos add, tf32-rounded fp32 output. grid = MROWS, block 256.
// ---------------------------------------------------------------------------
__global__ void bn_apply_kernel(const float* __restrict__ x,
                                const float* __restrict__ pos,
                                float* __restrict__ out, int coef_off)
{
    size_t row = blockIdx.x;
    int t = threadIdx.x;
    int c = (int)(row % 12);
    size_t b = row / 144;
    float A  = g_coef[coef_off + c];
    float Bc = g_coef[coef_off + 12 + c];
    float4 v = ((const float4*)(x + row * DIM))[t];
    float4 p = ((const float4*)(pos + (b * 12 + (size_t)c) * DIM))[t];
    float4 o;
    o.x = to_tf32(v.x * A + Bc + p.x);
    o.y = to_tf32(v.y * A + Bc + p.y);
    o.z = to_tf32(v.z * A + Bc + p.z);
    o.w = to_tf32(v.w * A + Bc + p.w);
    ((float4*)(out + row * DIM))[t] = o;
}

// ---------------------------------------------------------------------------
// LayerNorm -> tf32-rounded fp32 output. grid = MROWS, block 256.
// ---------------------------------------------------------------------------
__global__ void ln_kernel(const float* __restrict__ src, float* __restrict__ dst,
                          const float* __restrict__ w, const float* __restrict__ b)
{
    const size_t row = blockIdx.x;
    const int tid = threadIdx.x, lane = tid & 31, wrp = tid >> 5;
    __shared__ float ss[8], sq[8], mv[2];
    float4 v = ((const float4*)(src + row * DIM))[tid];
    float s = v.x + v.y + v.z + v.w;
    float q = v.x * v.x + v.y * v.y + v.z * v.z + v.w * v.w;
#pragma unroll
    for (int o = 16; o; o >>= 1) {
        s += __shfl_xor_sync(0xffffffffu, s, o);
        q += __shfl_xor_sync(0xffffffffu, q, o);
    }
    if (lane == 0) { ss[wrp] = s; sq[wrp] = q; }
    __syncthreads();
    if (tid == 0) {
        float S = 0.0f, Q = 0.0f;
#pragma unroll
        for (int i = 0; i < 8; i++) { S += ss[i]; Q += sq[i]; }
        float mean = S * (1.0f / 1024.0f);
        float var  = Q * (1.0f / 1024.0f) - mean * mean;
        mv[0] = mean;  mv[1] = rsqrtf(var + 1e-5f);
    }
    __syncthreads();
    float mean = mv[0], inv = mv[1];
    float4 wv = ((const float4*)w)[tid];
    float4 bv = ((const float4*)b)[tid];
    float4 o;
    o.x = to_tf32((v.x - mean) * inv * wv.x + bv.x);
    o.y = to_tf32((v.y - mean) * inv * wv.y + bv.y);
    o.z = to_tf32((v.z - mean) * inv * wv.z + bv.z);
    o.w = to_tf32((v.w - mean) * inv * wv.w + bv.w);
    ((float4*)(dst + row * DIM))[tid] = o;
}

// ---------------------------------------------------------------------------
// fused attention: logits(12x24) -> softmax -> attn @ V; tf32-rounded output
// ---------------------------------------------------------------------------
__global__ void attn_kernel(const float* __restrict__ q_r, const float* __restrict__ q_t,
                            const float* __restrict__ k_r, const float* __restrict__ k_t,
                            const float* __restrict__ v_r, const float* __restrict__ v_t,
                            float* __restrict__ ao_r, float* __restrict__ ao_t)
{
    const int bh = blockIdx.x;
    const bool tir = (blockIdx.y != 0);
    const size_t base = (size_t)bh * 12 * DIM;
    const float* Q = (tir ? q_t : q_r) + base;
    float* AO = (tir ? ao_t : ao_r) + base;
    const float* Kr = k_r + base;
    const float* Kt = k_t + base;
    const float* Vr = v_r + base;
    const float* Vt = v_t + base;

    __shared__ float att[12][24];
    const int tid = threadIdx.x, lane = tid & 31, wrp = tid >> 5;

    for (int dot = wrp; dot < 288; dot += 8) {
        int n1 = dot / 24, s = dot % 24;
        const float4* qp = (const float4*)(Q + (size_t)n1 * DIM);
        const float4* kp = (const float4*)((s < 12) ? (Kr + (size_t)s * DIM)
                                                    : (Kt + (size_t)(s - 12) * DIM));
        float acc = 0.0f;
        for (int d4 = lane; d4 < 256; d4 += 32) {
            float4 a = qp[d4]; float4 bb = kp[d4];
            acc += a.x * bb.x + a.y * bb.y + a.z * bb.z + a.w * bb.w;
        }
#pragma unroll
        for (int o = 16; o; o >>= 1) acc += __shfl_xor_sync(0xffffffffu, acc, o);
        if (lane == 0) att[n1][s] = acc;
    }
    __syncthreads();

    if (tid < 12) {
        const float scale = 0.03125f;
        float e[24], m = -1e30f;
#pragma unroll
        for (int s = 0; s < 24; s++) { float l = att[tid][s] * scale; e[s] = l; m = fmaxf(m, l); }
        float sum = 0.0f;
#pragma unroll
        for (int s = 0; s < 24; s++) { float x = expf(e[s] - m); e[s] = x; sum += x; }
        float inv = 1.0f / sum;
#pragma unroll
        for (int s = 0; s < 24; s++) att[tid][s] = e[s] * inv;
    }
    __syncthreads();

    for (int d = tid; d < DIM; d += 256) {
        float vc[24];
#pragma unroll
        for (int s = 0; s < 12; s++) vc[s]      = Vr[(size_t)s * DIM + d];
#pragma unroll
        for (int s = 0; s < 12; s++) vc[12 + s] = Vt[(size_t)s * DIM + d];
#pragma unroll
        for (int n1 = 0; n1 < 12; n1++) {
            float o = 0.0f;
#pragma unroll
            for (int s = 0; s < 24; s++) o += att[n1][s] * vc[s];
            AO[(size_t)n1 * DIM + d] = to_tf32(o);
        }
    }
}

// ---------------------------------------------------------------------------
extern "C" void kernel_launch(void* const* d_in, const int* in_sizes, int n_in,
                              void* d_out, int out_size)
{
    const float* attn_rgb = (const float*)d_in[0];
    const float* attn_tir = (const float*)d_in[1];
    const float* pos_emb  = (const float*)d_in[2];
    const float* embed_w  = (const float*)d_in[3];
    const float* embed_b  = (const float*)d_in[4];
    const float* bn_w     = (const float*)d_in[5];
    const float* bn_b     = (const float*)d_in[6];
    const float* ln_w     = (const float*)d_in[7];
    const float* ln_b     = (const float*)d_in[8];
    const float* v_w      = (const float*)d_in[9];
    const float* v_b      = (const float*)d_in[10];
    const float* q_w      = (const float*)d_in[11];
    const float* q_b      = (const float*)d_in[12];
    const float* k_w      = (const float*)d_in[13];
    const float* k_b      = (const float*)d_in[14];
    const float* out_w    = (const float*)d_in[15];
    const float* out_b    = (const float*)d_in[16];
    float* out = (float*)d_out;

    float* f32 = nullptr;   cudaGetSymbolAddress((void**)&f32, g_f32);
    float* wbuf = nullptr;  cudaGetSymbolAddress((void**)&wbuf, g_w);
    float* stats = nullptr; cudaGetSymbolAddress((void**)&stats, g_stats);

    float* in_r   = f32 + 0 * SLAB;   float* in_t   = f32 + 1 * SLAB;
    float* emb_r  = f32 + 2 * SLAB;   float* emb_t  = f32 + 3 * SLAB;
    float* norm_r = f32 + 4 * SLAB;   float* norm_t = f32 + 5 * SLAB;
    float* ln_r   = f32 + 6 * SLAB;   float* ln_t   = f32 + 7 * SLAB;
    float* ao_r   = ln_r;             float* ao_t   = ln_t;     // reuse after V GEMM
    float* q_rf   = f32 + 8 * SLAB;   float* q_tf   = f32 + 9 * SLAB;
    float* k_rf   = f32 + 10 * SLAB;  float* k_tf   = f32 + 11 * SLAB;
    float* v_rf   = f32 + 12 * SLAB;  float* v_tf   = f32 + 13 * SLAB;

    const size_t WN = 1024ULL * 1024;
    float* w_embed = wbuf + 0 * WN;
    float* w_v     = wbuf + 1 * WN;
    float* w_q     = wbuf + 2 * WN;
    float* w_k     = wbuf + 3 * WN;
    float* w_out   = wbuf + 4 * WN;

    cudaFuncSetAttribute(tgemm_kernel,
                         cudaFuncAttributeMaxDynamicSharedMemorySize, TF_SMEM);

    const dim3 gemm_grid(8, 288);   // n-tiles x m-tiles
    const int IN_BLKS = (int)(SLAB / 1024);   // 36864 blocks, float4/thread
    const int W_BLKS  = (int)(WN / 1024);     // 1024 blocks

    zero_stats_kernel<<<1, 64>>>();

    // tf32 RN rounding of weights and raw inputs
    cvt_tf32_kernel<<<W_BLKS, 256>>>(embed_w, w_embed);
    cvt_tf32_kernel<<<W_BLKS, 256>>>(v_w, w_v);
    cvt_tf32_kernel<<<W_BLKS, 256>>>(q_w, w_q);
    cvt_tf32_kernel<<<W_BLKS, 256>>>(k_w, w_k);
    cvt_tf32_kernel<<<W_BLKS, 256>>>(out_w, w_out);
    cvt_tf32_kernel<<<IN_BLKS, 256>>>(attn_rgb, in_r);
    cvt_tf32_kernel<<<IN_BLKS, 256>>>(attn_tir, in_t);

    // embed GEMMs
    tgemm_kernel<<<gemm_grid, 256, TF_SMEM>>>(in_r, w_embed, embed_b, emb_r);
    tgemm_kernel<<<gemm_grid, 256, TF_SMEM>>>(in_t, w_embed, embed_b, emb_t);

    // BN stats + apply (+pos) -> tf32-rounded norm buffers
    bn_stats_kernel<<<BHCOUNT, 256>>>(emb_r, stats + 0,  stats + 12);
    bn_stats_kernel<<<BHCOUNT, 256>>>(emb_t, stats + 24, stats + 36);
    bn_finalize_kernel<<<1, 32>>>(bn_w, bn_b);
    bn_apply_kernel<<<MROWS, 256>>>(emb_r, pos_emb, norm_r, 0);
    bn_apply_kernel<<<MROWS, 256>>>(emb_t, pos_emb, norm_t, 24);

    // LN (raw inputs) -> tf32, then V GEMMs
    ln_kernel<<<MROWS, 256>>>(attn_rgb, ln_r, ln_w, ln_b);
    ln_kernel<<<MROWS, 256>>>(attn_tir, ln_t, ln_w, ln_b);
    tgemm_kernel<<<gemm_grid, 256, TF_SMEM>>>(ln_r, w_v, v_b, v_rf);
    tgemm_kernel<<<gemm_grid, 256, TF_SMEM>>>(ln_t, w_v, v_b, v_tf);

    // Q and K GEMMs from normed buffers
    tgemm_kernel<<<gemm_grid, 256, TF_SMEM>>>(norm_r, w_q, q_b, q_rf);
    tgemm_kernel<<<gemm_grid, 256, TF_SMEM>>>(norm_t, w_q, q_b, q_tf);
    tgemm_kernel<<<gemm_grid, 256, TF_SMEM>>>(norm_r, w_k, k_b, k_rf);
    tgemm_kernel<<<gemm_grid, 256, TF_SMEM>>>(norm_t, w_k, k_b, k_tf);

    // fused attention -> tf32-rounded outputs (overwrites ln buffers)
    attn_kernel<<<dim3(BHCOUNT, 2), 256>>>(q_rf, q_tf, k_rf, k_tf, v_rf, v_tf,
                                           ao_r, ao_t);

    // output projections straight into d_out
    tgemm_kernel<<<gemm_grid, 256, TF_SMEM>>>(ao_r, w_out, out_b, out);
    tgemm_kernel<<<gemm_grid, 256, TF_SMEM>>>(ao_t, w_out, out_b, out + SLAB);
}

// round 13
// speedup vs baseline: 3.8511x; 1.0459x over previous
#include <cuda_runtime.h>
#include <cuda_bf16.h>
#include <math.h>
#include <stdint.h>

// Shapes: B=256, hn=12, N1=12, dim=inner=1024
#define MROWS   36864
#define BHCOUNT 3072
#define DIM     1024
#define SLAB    37748736ULL          // MROWS * DIM

// fp32 slabs: 0 emb_r, 1 emb_t, 2 norm_r, 3 norm_t, 4 ln_r(->ao_r), 5 ln_t(->ao_t),
//             6 q_r, 7 q_t, 8 k_r, 9 k_t, 10 v_r, 11 v_t   (pairs adjacent!)
__device__ float g_f32[12 * SLAB];
__device__ float g_w[5ULL * 1024 * 1024];   // tf32-rounded weights
__device__ float g_stats[48];   // [0:12) sum_r, [12:24) sq_r, [24:36) sum_t, [36:48) sq_t
__device__ float g_coef[48];

// ---------------------------------------------------------------------------
__global__ void zero_stats_kernel() {
    if (threadIdx.x < 48) g_stats[threadIdx.x] = 0.0f;
}

// ---------------------------------------------------------------------------
// helpers
// ---------------------------------------------------------------------------
__device__ __forceinline__ uint32_t swz128(uint32_t o) { return o ^ ((o >> 3) & 0x70); }

__device__ __forceinline__ void cp_async16(uint32_t saddr, const void* gaddr) {
    asm volatile("cp.async.cg.shared.global [%0], [%1], 16;\n" :: "r"(saddr), "l"(gaddr));
}
__device__ __forceinline__ void cp_commit() { asm volatile("cp.async.commit_group;\n"); }

__device__ __forceinline__ float to_tf32(float x) {
    float r;
    asm("cvt.rna.tf32.f32 %0, %1;" : "=f"(r) : "f"(x));
    return r;
}
__device__ __forceinline__ uint32_t round_u32(uint32_t x) {
    return __float_as_uint(to_tf32(__uint_as_float(x)));
}

__device__ __forceinline__ void ldsm4(uint32_t& r0, uint32_t& r1, uint32_t& r2,
                                      uint32_t& r3, uint32_t addr) {
    asm volatile("ldmatrix.sync.aligned.m8n8.x4.shared.b16 {%0,%1,%2,%3}, [%4];\n"
                 : "=r"(r0), "=r"(r1), "=r"(r2), "=r"(r3) : "r"(addr));
}

__device__ __forceinline__ void mma_tf32(float* d, const uint32_t* a, const uint32_t* b) {
    asm volatile(
        "mma.sync.aligned.m16n8k8.row.col.f32.tf32.tf32.f32 "
        "{%0,%1,%2,%3},{%4,%5,%6,%7},{%8,%9},{%0,%1,%2,%3};\n"
        : "+f"(d[0]), "+f"(d[1]), "+f"(d[2]), "+f"(d[3])
        : "r"(a[0]), "r"(a[1]), "r"(a[2]), "r"(a[3]), "r"(b[0]), "r"(b[1]));
}

__device__ __forceinline__ uint32_t smem_u32(const void* p) {
    uint32_t a;
    asm("{ .reg .u64 t; cvta.to.shared.u64 t, %1; cvt.u32.u64 %0, t; }" : "=r"(a) : "l"(p));
    return a;
}

// ---------------------------------------------------------------------------
// round an fp32 array to tf32 (RN). grid = n/1024, block 256, float4/thread.
// ---------------------------------------------------------------------------
__global__ void cvt_tf32_kernel(const float* __restrict__ in, float* __restrict__ out)
{
    size_t i = ((size_t)blockIdx.x * 256 + threadIdx.x) * 4;
    float4 v = *(const float4*)(in + i);
    v.x = to_tf32(v.x); v.y = to_tf32(v.y);
    v.z = to_tf32(v.z); v.w = to_tf32(v.w);
    *(float4*)(out + i) = v;
}

// ---------------------------------------------------------------------------
// tf32 GEMM: C[M,1024] = A @ W^T + bias.
// ROUND_A: RN-round A fragments in registers (A is raw fp32).
// DO_STATS: accumulate per-channel (row%12) sum / sumsq of C into statsPtr.
// Block tile 128x128, k-tile 32 floats, 3-stage cp.async, prefetch-2,
// ONE __syncthreads per k-tile. 256 threads, 8 warps, warp tile 32x64.
// ---------------------------------------------------------------------------
#define TFSTAGE 32768
#define TF_SMEM (3 * TFSTAGE)

template<bool ROUND_A, bool DO_STATS>
__global__ __launch_bounds__(256, 2) void tgemm_kernel(
    const float* __restrict__ A, const float* __restrict__ W,
    const float* __restrict__ bias, float* __restrict__ C,
    float* __restrict__ statsPtr)
{
    extern __shared__ char smem[];
    __shared__ float s_sum[128], s_sq[128];
    const uint32_t tiles = smem_u32(smem);
    const int tid = threadIdx.x, lane = tid & 31, warp = tid >> 5;
    const int bm = blockIdx.y, bn = blockIdx.x;
    const int m_off = (warp >> 1) * 32, n_off = (warp & 1) * 64;
    const int r0 = tid >> 3;     // 0..31
    const int ch = tid & 7;      // 16B chunk within 128B row

    if (DO_STATS) {
        if (tid < 128) { s_sum[tid] = 0.0f; s_sq[tid] = 0.0f; }
    }

    float acc[2][8][4];
#pragma unroll
    for (int i = 0; i < 2; i++)
#pragma unroll
        for (int j = 0; j < 8; j++)
#pragma unroll
            for (int r = 0; r < 4; r++) acc[i][j][r] = 0.0f;

    auto load_tile = [&](int stage, int kt) {
        const float* Ag = A + (size_t)(bm * 128 + r0) * DIM + kt * 32 + ch * 4;
        const float* Wg = W + (size_t)(bn * 128 + r0) * DIM + kt * 32 + ch * 4;
        uint32_t sa = tiles + stage * TFSTAGE;
        uint32_t sb = sa + 16384;
#pragma unroll
        for (int j = 0; j < 4; j++) {
            uint32_t so = swz128((uint32_t)(r0 + 32 * j) * 128 + ch * 16);
            cp_async16(sa + so, Ag + (size_t)(32 * j) * DIM);
            cp_async16(sb + so, Wg + (size_t)(32 * j) * DIM);
        }
        cp_commit();
    };

    load_tile(0, 0); load_tile(1, 1);

#pragma unroll 1
    for (int kt = 0; kt < 32; kt++) {
        if (kt < 31) asm volatile("cp.async.wait_group 1;\n" ::: "memory");
        else         asm volatile("cp.async.wait_group 0;\n" ::: "memory");
        __syncthreads();

        // issue next tile into the slot last read at iter kt-1 (all threads past barrier)
        if (kt + 2 < 32) load_tile((kt + 2) % 3, kt + 2);

        uint32_t sa = tiles + (kt % 3) * TFSTAGE;
        uint32_t sb = sa + 16384;
#pragma unroll
        for (int kk = 0; kk < 4; kk++) {           // 4 k8 steps per 32-float tile
            uint32_t afr[2][4], bfr[8][2];
#pragma unroll
            for (int i = 0; i < 2; i++) {
                int row = m_off + i * 16 + (lane & 15);
                uint32_t addr = sa + swz128((uint32_t)row * 128 + (2 * kk + (lane >> 4)) * 16);
                ldsm4(afr[i][0], afr[i][1], afr[i][2], afr[i][3], addr);
                if (ROUND_A) {
#pragma unroll
                    for (int r = 0; r < 4; r++) afr[i][r] = round_u32(afr[i][r]);
                }
            }
#pragma unroll
            for (int jj = 0; jj < 4; jj++) {
                int row = n_off + jj * 16 + (lane & 7) + ((lane >> 4) << 3);
                uint32_t addr = sb + swz128((uint32_t)row * 128 + (2 * kk + ((lane >> 3) & 1)) * 16);
                ldsm4(bfr[2 * jj][0], bfr[2 * jj][1], bfr[2 * jj + 1][0], bfr[2 * jj + 1][1], addr);
            }
#pragma unroll
            for (int i = 0; i < 2; i++)
#pragma unroll
                for (int j = 0; j < 8; j++) mma_tf32(acc[i][j], afr[i], bfr[j]);
        }
    }

    // epilogue
    const int gr = lane >> 2, gc = (lane & 3) * 2;
    float rsum[4] = {0, 0, 0, 0}, rsq[4] = {0, 0, 0, 0};
#pragma unroll
    for (int i = 0; i < 2; i++) {
        size_t rowg = (size_t)(bm * 128 + m_off + i * 16 + gr);
#pragma unroll
        for (int j = 0; j < 8; j++) {
            int col = bn * 128 + n_off + j * 8 + gc;
            float b0 = __ldg(bias + col), b1 = __ldg(bias + col + 1);
            float2 o0 = make_float2(acc[i][j][0] + b0, acc[i][j][1] + b1);
            float2 o1 = make_float2(acc[i][j][2] + b0, acc[i][j][3] + b1);
            *(float2*)(C + rowg * DIM + col)       = o0;
            *(float2*)(C + (rowg + 8) * DIM + col) = o1;
            if (DO_STATS) {
                rsum[2 * i]     += o0.x + o0.y;
                rsq[2 * i]      += o0.x * o0.x + o0.y * o0.y;
                rsum[2 * i + 1] += o1.x + o1.y;
                rsq[2 * i + 1]  += o1.x * o1.x + o1.y * o1.y;
            }
        }
    }

    if (DO_STATS) {
#pragma unroll
        for (int i = 0; i < 2; i++) {
            int lr = m_off + i * 16 + gr;
            atomicAdd(&s_sum[lr],     rsum[2 * i]);
            atomicAdd(&s_sq[lr],      rsq[2 * i]);
            atomicAdd(&s_sum[lr + 8], rsum[2 * i + 1]);
            atomicAdd(&s_sq[lr + 8],  rsq[2 * i + 1]);
        }
        __syncthreads();
        if (tid < 128) {
            int c = (bm * 128 + tid) % 12;
            atomicAdd(&statsPtr[c],      s_sum[tid]);
            atomicAdd(&statsPtr[12 + c], s_sq[tid]);
        }
    }
}

// ---------------------------------------------------------------------------
// BN finalize: stats -> per-channel affine coefficients (both streams)
// ---------------------------------------------------------------------------
__global__ void bn_finalize_kernel(const float* __restrict__ bn_w,
                                   const float* __restrict__ bn_b)
{
    int c = threadIdx.x;
    if (c >= 12) return;
    const float inv_cnt = 1.0f / 3145728.0f;
    {
        float mean = g_stats[c] * inv_cnt;
        float var  = g_stats[12 + c] * inv_cnt - mean * mean;
        float A = bn_w[c] * rsqrtf(var + 1e-5f);
        g_coef[c] = A;  g_coef[12 + c] = bn_b[c] - mean * A;
    }
    {
        float mean = g_stats[24 + c] * inv_cnt;
        float var  = g_stats[36 + c] * inv_cnt - mean * mean;
        float A = bn_w[c] * rsqrtf(var + 1e-5f);
        g_coef[24 + c] = A;  g_coef[36 + c] = bn_b[c] - mean * A;
    }
}

// ---------------------------------------------------------------------------
// BN apply + pos add, tf32-rounded fp32 output. BOTH streams in one launch:
// grid = 2*MROWS; emb slabs and norm slabs are each adjacent pairs.
// ---------------------------------------------------------------------------
__global__ void bn_apply_kernel(const float* __restrict__ emb,   // slab 0 (r|t)
                                const float* __restrict__ pos,
                                float* __restrict__ normout)     // slab 2 (r|t)
{
    size_t row = blockIdx.x;             // 0 .. 2*MROWS-1
    int t = threadIdx.x;
    int stream = (int)(row >= MROWS);
    size_t lrow = row - (size_t)stream * MROWS;
    int coef_off = stream * 24;
    int c = (int)(lrow % 12);
    size_t b = lrow / 144;
    float A  = g_coef[coef_off + c];
    float Bc = g_coef[coef_off + 12 + c];
    float4 v = ((const float4*)(emb + row * DIM))[t];
    float4 p = ((const float4*)(pos + (b * 12 + (size_t)c) * DIM))[t];
    float4 o;
    o.x = to_tf32(v.x * A + Bc + p.x);
    o.y = to_tf32(v.y * A + Bc + p.y);
    o.z = to_tf32(v.z * A + Bc + p.z);
    o.w = to_tf32(v.w * A + Bc + p.w);
    ((float4*)(normout + row * DIM))[t] = o;
}

// ---------------------------------------------------------------------------
// LayerNorm -> tf32-rounded fp32 output. grid = MROWS, block 256.
// ---------------------------------------------------------------------------
__global__ void ln_kernel(const float* __restrict__ src, float* __restrict__ dst,
                          const float* __restrict__ w, const float* __restrict__ b)
{
    const size_t row = blockIdx.x;
    const int tid = threadIdx.x, lane = tid & 31, wrp = tid >> 5;
    __shared__ float ss[8], sq[8], mv[2];
    float4 v = ((const float4*)(src + row * DIM))[tid];
    float s = v.x + v.y + v.z + v.w;
    float q = v.x * v.x + v.y * v.y + v.z * v.z + v.w * v.w;
#pragma unroll
    for (int o = 16; o; o >>= 1) {
        s += __shfl_xor_sync(0xffffffffu, s, o);
        q += __shfl_xor_sync(0xffffffffu, q, o);
    }
    if (lane == 0) { ss[wrp] = s; sq[wrp] = q; }
    __syncthreads();
    if (tid == 0) {
        float S = 0.0f, Q = 0.0f;
#pragma unroll
        for (int i = 0; i < 8; i++) { S += ss[i]; Q += sq[i]; }
        float mean = S * (1.0f / 1024.0f);
        float var  = Q * (1.0f / 1024.0f) - mean * mean;
        mv[0] = mean;  mv[1] = rsqrtf(var + 1e-5f);
    }
    __syncthreads();
    float mean = mv[0], inv = mv[1];
    float4 wv = ((const float4*)w)[tid];
    float4 bv = ((const float4*)b)[tid];
    float4 o;
    o.x = to_tf32((v.x - mean) * inv * wv.x + bv.x);
    o.y = to_tf32((v.y - mean) * inv * wv.y + bv.y);
    o.z = to_tf32((v.z - mean) * inv * wv.z + bv.z);
    o.w = to_tf32((v.w - mean) * inv * wv.w + bv.w);
    ((float4*)(dst + row * DIM))[tid] = o;
}

// ---------------------------------------------------------------------------
// fused attention: logits(12x24) -> softmax -> attn @ V; tf32-rounded output
// ---------------------------------------------------------------------------
__global__ void attn_kernel(const float* __restrict__ q_r, const float* __restrict__ q_t,
                            const float* __restrict__ k_r, const float* __restrict__ k_t,
                            const float* __restrict__ v_r, const float* __restrict__ v_t,
                            float* __restrict__ ao_r, float* __restrict__ ao_t)
{
    const int bh = blockIdx.x;
    const bool tir = (blockIdx.y != 0);
    const size_t base = (size_t)bh * 12 * DIM;
    const float* Q = (tir ? q_t : q_r) + base;
    float* AO = (tir ? ao_t : ao_r) + base;
    const float* Kr = k_r + base;
    const float* Kt = k_t + base;
    const float* Vr = v_r + base;
    const float* Vt = v_t + base;

    __shared__ float att[12][24];
    const int tid = threadIdx.x, lane = tid & 31, wrp = tid >> 5;

    for (int dot = wrp; dot < 288; dot += 8) {
        int n1 = dot / 24, s = dot % 24;
        const float4* qp = (const float4*)(Q + (size_t)n1 * DIM);
        const float4* kp = (const float4*)((s < 12) ? (Kr + (size_t)s * DIM)
                                                    : (Kt + (size_t)(s - 12) * DIM));
        float acc = 0.0f;
        for (int d4 = lane; d4 < 256; d4 += 32) {
            float4 a = qp[d4]; float4 bb = kp[d4];
            acc += a.x * bb.x + a.y * bb.y + a.z * bb.z + a.w * bb.w;
        }
#pragma unroll
        for (int o = 16; o; o >>= 1) acc += __shfl_xor_sync(0xffffffffu, acc, o);
        if (lane == 0) att[n1][s] = acc;
    }
    __syncthreads();

    if (tid < 12) {
        const float scale = 0.03125f;
        float e[24], m = -1e30f;
#pragma unroll
        for (int s = 0; s < 24; s++) { float l = att[tid][s] * scale; e[s] = l; m = fmaxf(m, l); }
        float sum = 0.0f;
#pragma unroll
        for (int s = 0; s < 24; s++) { float x = expf(e[s] - m); e[s] = x; sum += x; }
        float inv = 1.0f / sum;
#pragma unroll
        for (int s = 0; s < 24; s++) att[tid][s] = e[s] * inv;
    }
    __syncthreads();

    for (int d = tid; d < DIM; d += 256) {
        float vc[24];
#pragma unroll
        for (int s = 0; s < 12; s++) vc[s]      = Vr[(size_t)s * DIM + d];
#pragma unroll
        for (int s = 0; s < 12; s++) vc[12 + s] = Vt[(size_t)s * DIM + d];
#pragma unroll
        for (int n1 = 0; n1 < 12; n1++) {
            float o = 0.0f;
#pragma unroll
            for (int s = 0; s < 24; s++) o += att[n1][s] * vc[s];
            AO[(size_t)n1 * DIM + d] = to_tf32(o);
        }
    }
}

// ---------------------------------------------------------------------------
extern "C" void kernel_launch(void* const* d_in, const int* in_sizes, int n_in,
                              void* d_out, int out_size)
{
    const float* attn_rgb = (const float*)d_in[0];
    const float* attn_tir = (const float*)d_in[1];
    const float* pos_emb  = (const float*)d_in[2];
    const float* embed_w  = (const float*)d_in[3];
    const float* embed_b  = (const float*)d_in[4];
    const float* bn_w     = (const float*)d_in[5];
    const float* bn_b     = (const float*)d_in[6];
    const float* ln_w     = (const float*)d_in[7];
    const float* ln_b     = (const float*)d_in[8];
    const float* v_w      = (const float*)d_in[9];
    const float* v_b      = (const float*)d_in[10];
    const float* q_w      = (const float*)d_in[11];
    const float* q_b      = (const float*)d_in[12];
    const float* k_w      = (const float*)d_in[13];
    const float* k_b      = (const float*)d_in[14];
    const float* out_w    = (const float*)d_in[15];
    const float* out_b    = (const float*)d_in[16];
    float* out = (float*)d_out;

    float* f32 = nullptr;   cudaGetSymbolAddress((void**)&f32, g_f32);
    float* wbuf = nullptr;  cudaGetSymbolAddress((void**)&wbuf, g_w);
    float* stats = nullptr; cudaGetSymbolAddress((void**)&stats, g_stats);

    float* emb   = f32 + 0 * SLAB;    // [0,1]: emb_r | emb_t
    float* norm  = f32 + 2 * SLAB;    // [2,3]: norm_r | norm_t
    float* lns   = f32 + 4 * SLAB;    // [4,5]: ln_r | ln_t  (reused as ao after V)
    float* qbuf  = f32 + 6 * SLAB;    // [6,7]
    float* kbuf  = f32 + 8 * SLAB;    // [8,9]
    float* vbuf  = f32 + 10 * SLAB;   // [10,11]

    const size_t WN = 1024ULL * 1024;
    float* w_embed = wbuf + 0 * WN;
    float* w_v     = wbuf + 1 * WN;
    float* w_q     = wbuf + 2 * WN;
    float* w_k     = wbuf + 3 * WN;
    float* w_out   = wbuf + 4 * WN;

    cudaFuncSetAttribute(tgemm_kernel<false, false>,
                         cudaFuncAttributeMaxDynamicSharedMemorySize, TF_SMEM);
    cudaFuncSetAttribute(tgemm_kernel<true, true>,
                         cudaFuncAttributeMaxDynamicSharedMemorySize, TF_SMEM);

    const dim3 grid1(8, 288);    // single-stream GEMM (M = 36864)
    const dim3 grid2(8, 576);    // merged-pair GEMM  (M = 73728)
    const int W_BLKS = (int)(WN / 1024);

    zero_stats_kernel<<<1, 64>>>();

    // tf32 RN rounding of weights (inputs are rounded in-register by embed GEMMs)
    cvt_tf32_kernel<<<W_BLKS, 256>>>(embed_w, w_embed);
    cvt_tf32_kernel<<<W_BLKS, 256>>>(v_w, w_v);
    cvt_tf32_kernel<<<W_BLKS, 256>>>(q_w, w_q);
    cvt_tf32_kernel<<<W_BLKS, 256>>>(k_w, w_k);
    cvt_tf32_kernel<<<W_BLKS, 256>>>(out_w, w_out);

    // LN of raw inputs (independent of embed path)
    ln_kernel<<<MROWS, 256>>>(attn_rgb, lns, ln_w, ln_b);
    ln_kernel<<<MROWS, 256>>>(attn_tir, lns + SLAB, ln_w, ln_b);

    // embed GEMMs: raw A, fragment rounding, fused BN stats
    tgemm_kernel<true, true><<<grid1, 256, TF_SMEM>>>(attn_rgb, w_embed, embed_b,
                                                      emb, stats + 0);
    tgemm_kernel<true, true><<<grid1, 256, TF_SMEM>>>(attn_tir, w_embed, embed_b,
                                                      emb + SLAB, stats + 24);

    // BN finalize + apply (+pos), both streams in one launch
    bn_finalize_kernel<<<1, 32>>>(bn_w, bn_b);
    bn_apply_kernel<<<2 * MROWS, 256>>>(emb, pos_emb, norm);

    // V GEMM (merged pair), Q and K GEMMs (merged pairs)
    tgemm_kernel<false, false><<<grid2, 256, TF_SMEM>>>(lns, w_v, v_b, vbuf, nullptr);
    tgemm_kernel<false, false><<<grid2, 256, TF_SMEM>>>(norm, w_q, q_b, qbuf, nullptr);
    tgemm_kernel<false, false><<<grid2, 256, TF_SMEM>>>(norm, w_k, k_b, kbuf, nullptr);

    // fused attention -> tf32-rounded outputs (overwrites ln slabs)
    attn_kernel<<<dim3(BHCOUNT, 2), 256>>>(qbuf, qbuf + SLAB, kbuf, kbuf + SLAB,
                                           vbuf, vbuf + SLAB, lns, lns + SLAB);

    // output projection (merged pair) straight into d_out
    tgemm_kernel<false, false><<<grid2, 256, TF_SMEM>>>(lns, w_out, out_b, out, nullptr);
}